// round 7
// baseline (speedup 1.0000x reference)
#include <cuda_runtime.h>
#include <cuda_bf16.h>
#include <cstdint>
#include <cstddef>

#define B_   16
#define NPT  4096
#define SPT  1024
#define D1_  256
#define D2_  128
#define CIN  384
#define CO   256
#define NS   (B_*NPT)   // 65536

// ---------------------------------------------------------------------------
// Scratch
// ---------------------------------------------------------------------------
__device__ float         g_p2t[B_ * SPT * D2_];
__device__ __nv_bfloat16 g_x1h[(size_t)NS * CIN];
__device__ __nv_bfloat16 g_x1l[(size_t)NS * CIN];
__device__ __nv_bfloat16 g_x2h[(size_t)NS * CO];
__device__ __nv_bfloat16 g_x2l[(size_t)NS * CO];
__device__ float         g_y1[(size_t)NS * CO];     // y1, then reused as y2
__device__ __nv_bfloat16 g_w1h[CO * CIN], g_w1l[CO * CIN];
__device__ __nv_bfloat16 g_w2h[CO * CO],  g_w2l[CO * CO];
__device__ float g_psum[256 * 512], g_psq[256 * 512];   // per-mtile partials
__device__ float g_a1[CO], g_b1[CO], g_a2[CO], g_b2[CO];
__device__ float4 g_nnw4[NS];   // 3 normalized weights per query
__device__ int4   g_nni4[NS];   // 3 neighbor indices per query

__device__ __forceinline__ uint32_t smem_u32(const void* p) {
    uint32_t a;
    asm("{ .reg .u64 t; cvta.to.shared.u64 t, %1; cvt.u32.u64 %0, t; }" : "=r"(a) : "l"(p));
    return a;
}
__device__ __forceinline__ void split_bf16(float a, uint32_t& h, uint32_t& l) {
    __nv_bfloat16 hb = __float2bfloat16(a);
    __nv_bfloat16 lb = __float2bfloat16(a - __bfloat162float(hb));
    h = (uint32_t)__bfloat16_as_ushort(hb);
    l = (uint32_t)__bfloat16_as_ushort(lb);
}

// ---------------------------------------------------------------------------
// W split
// ---------------------------------------------------------------------------
__global__ void k_wsplit(const float* __restrict__ W1, const float* __restrict__ W2) {
    const int i = blockIdx.x * 256 + threadIdx.x;
    uint32_t h, l;
    if (i < CO * CIN) {
        split_bf16(W1[i], h, l);
        g_w1h[i] = __ushort_as_bfloat16((unsigned short)h);
        g_w1l[i] = __ushort_as_bfloat16((unsigned short)l);
    } else {
        const int j = i - CO * CIN;
        split_bf16(W2[j], h, l);
        g_w2h[j] = __ushort_as_bfloat16((unsigned short)h);
        g_w2l[j] = __ushort_as_bfloat16((unsigned short)l);
    }
}

// ---------------------------------------------------------------------------
// transpose points2 [B,D2,S] -> g_p2t [B,S,D2]
// ---------------------------------------------------------------------------
__global__ void k_tp2(const float* __restrict__ p2) {
    __shared__ float t[32][33];
    const int b = blockIdx.z, c0 = blockIdx.y * 32, s0 = blockIdx.x * 32;
    const int tx = threadIdx.x, ty = threadIdx.y;
#pragma unroll
    for (int i = 0; i < 4; i++)
        t[ty + i * 8][tx] = p2[((size_t)b * D2_ + c0 + ty + i * 8) * SPT + s0 + tx];
    __syncthreads();
#pragma unroll
    for (int i = 0; i < 4; i++)
        g_p2t[((size_t)b * SPT + s0 + ty + i * 8) * D2_ + c0 + tx] = t[tx][ty + i * 8];
}

// ---------------------------------------------------------------------------
// transpose+split points1 [B,256,N] -> X1 cols [0,256)
// ---------------------------------------------------------------------------
__global__ void k_tp1(const float* __restrict__ p1) {
    __shared__ float t[32][33];
    const int b = blockIdx.z, c0 = blockIdx.y * 32, n0 = blockIdx.x * 32;
    const int tx = threadIdx.x, ty = threadIdx.y;
    const int tid = ty * 32 + tx;
#pragma unroll
    for (int i = 0; i < 4; i++)
        t[ty + i * 8][tx] = p1[((size_t)b * D1_ + c0 + ty + i * 8) * NPT + n0 + tx];
    __syncthreads();
#pragma unroll
    for (int w = 0; w < 2; w++) {
        const int v = w * 256 + tid;
        const int n = v >> 4, u = v & 15;
        uint32_t h0, l0, h1, l1;
        split_bf16(t[2 * u][n], h0, l0);
        split_bf16(t[2 * u + 1][n], h1, l1);
        const size_t a = (size_t)(b * NPT + n0 + n) * CIN + c0 + 2 * u;
        *(uint32_t*)(g_x1h + a) = h0 | (h1 << 16);
        *(uint32_t*)(g_x1l + a) = l0 | (l1 << 16);
    }
}

// ---------------------------------------------------------------------------
// k_nn: branchless 3-NN. xyz2 staged as (x,y,z,|b|^2) float4; compare
// d' = |b|^2 - 2 a.b (|a|^2 constant per query, added only at the end).
// ---------------------------------------------------------------------------
__global__ void __launch_bounds__(256) k_nn(const float* __restrict__ xyz1,
                                            const float* __restrict__ xyz2) {
    __shared__ float4 s2[SPT];
    const int b = blockIdx.y, tid = threadIdx.x;
    const int n = blockIdx.x * 256 + tid;
    for (int i = tid; i < SPT; i += 256) {
        const float x = xyz2[(size_t)b * 3072 + i];
        const float y = xyz2[(size_t)b * 3072 + 1024 + i];
        const float z = xyz2[(size_t)b * 3072 + 2048 + i];
        s2[i] = make_float4(x, y, z, fmaf(x, x, fmaf(y, y, z * z)));
    }
    __syncthreads();

    const float px = xyz1[((size_t)b * 3 + 0) * NPT + n];
    const float py = xyz1[((size_t)b * 3 + 1) * NPT + n];
    const float pz = xyz1[((size_t)b * 3 + 2) * NPT + n];
    const float mx = -2.f * px, my = -2.f * py, mz = -2.f * pz;
    const float a2 = fmaf(px, px, fmaf(py, py, pz * pz));

    float d0 = 1e30f, d1 = 1e30f, d2 = 1e30f;
    int   i0 = 0, i1 = 0, i2 = 0;
#pragma unroll 4
    for (int s = 0; s < SPT; s++) {
        const float4 v = s2[s];
        const float d = fmaf(mx, v.x, fmaf(my, v.y, fmaf(mz, v.z, v.w)));
        const bool p0 = d < d0, p1 = d < d1, p2 = d < d2;
        i2 = p1 ? i1 : (p2 ? s : i2);
        d2 = p1 ? d1 : (p2 ? d : d2);
        i1 = p0 ? i0 : (p1 ? s : i1);
        d1 = p0 ? d0 : (p1 ? d : d1);
        i0 = p0 ? s : i0;
        d0 = p0 ? d : d0;
    }
    const float f0 = sqrtf(fmaxf(d0 + a2, 0.f));
    const float f1 = sqrtf(fmaxf(d1 + a2, 0.f));
    const float f2 = sqrtf(fmaxf(d2 + a2, 0.f));
    float w0 = 1.f / (f0 + 1e-10f);
    float w1 = 1.f / (f1 + 1e-10f);
    float w2 = 1.f / (f2 + 1e-10f);
    const float inv = 1.f / (w0 + w1 + w2);
    const int q = b * NPT + n;
    g_nnw4[q] = make_float4(w0 * inv, w1 * inv, w2 * inv, 0.f);
    g_nni4[q] = make_int4(i0, i1, i2, 0);
}

// ---------------------------------------------------------------------------
// k_gather: warp per query; register accumulation; bf16 hi/lo out (X1 cols
// [256,384)). Rows of g_p2t are 512B contiguous -> coalesced per warp.
// ---------------------------------------------------------------------------
__global__ void __launch_bounds__(256) k_gather() {
    const int wid = threadIdx.x >> 5, lane = threadIdx.x & 31;
    const int n = blockIdx.x * 8 + wid;           // global query id
    const int b = n >> 12;
    const float4 wv = g_nnw4[n];
    const int4   iv = g_nni4[n];
    const float* p2t = g_p2t + (size_t)b * SPT * D2_;
    const float4 v0 = *(const float4*)(p2t + (size_t)iv.x * D2_ + lane * 4);
    const float4 v1 = *(const float4*)(p2t + (size_t)iv.y * D2_ + lane * 4);
    const float4 v2 = *(const float4*)(p2t + (size_t)iv.z * D2_ + lane * 4);
    float4 a;
    a.x = fmaf(wv.x, v0.x, fmaf(wv.y, v1.x, wv.z * v2.x));
    a.y = fmaf(wv.x, v0.y, fmaf(wv.y, v1.y, wv.z * v2.y));
    a.z = fmaf(wv.x, v0.z, fmaf(wv.y, v1.z, wv.z * v2.z));
    a.w = fmaf(wv.x, v0.w, fmaf(wv.y, v1.w, wv.z * v2.w));
    uint32_t h0, l0, h1, l1, h2, l2, h3, l3;
    split_bf16(a.x, h0, l0); split_bf16(a.y, h1, l1);
    split_bf16(a.z, h2, l2); split_bf16(a.w, h3, l3);
    const size_t o = (size_t)n * CIN + D1_ + lane * 4;
    *(uint2*)(g_x1h + o) = make_uint2(h0 | (h1 << 16), h2 | (h3 << 16));
    *(uint2*)(g_x1l + o) = make_uint2(l0 | (l1 << 16), l2 | (l3 << 16));
}

// ---------------------------------------------------------------------------
// Warp-MMA GEMM + fused per-CTA BN stat partials.
// C[n,256] = X[n,K] * W[256,K]^T ; CTA 128x128, K-chunk 64, cp.async double
// buffer, 8 warps 4(M)x2(N). Epilogue reduces column sums of y and y^2 via
// shfl + smem, writes deterministic partials g_psum/g_psq[(chan)*512+mtile].
// ---------------------------------------------------------------------------
#define MMA_SMEM (2 * 65536 + 1024)

template <int LAYER>
__global__ void __launch_bounds__(256) k_mma() {
    constexpr int K  = (LAYER == 1) ? CIN : CO;
    constexpr int KT = K / 64;
    const __nv_bfloat16* xh = (LAYER == 1) ? g_x1h : g_x2h;
    const __nv_bfloat16* xl = (LAYER == 1) ? g_x1l : g_x2l;
    const __nv_bfloat16* wh = (LAYER == 1) ? g_w1h : g_w2h;
    const __nv_bfloat16* wl = (LAYER == 1) ? g_w1l : g_w2l;
    float* C = g_y1;

    extern __shared__ uint8_t dsm[];
    const uint32_t sbase = (smem_u32(dsm) + 1023) & ~1023u;
    __shared__ float sm_s[4][128], sm_q[4][128];

    const int tid  = threadIdx.x, wid = tid >> 5, lane = tid & 31;
    const int m0   = blockIdx.x << 7;
    const int n0   = blockIdx.y << 7;
    const int wm   = wid & 3, wn = wid >> 2;

    auto stage = [&](int kt) {
        const int buf = kt & 1;
        const uint32_t base = sbase + buf * 65536;
        const int k0 = kt * 64;
#pragma unroll
        for (int i = 0; i < 16; i++) {
            const int q = tid + i * 256;
            const int sel = q >> 10;
            const int r = (q & 1023) >> 3, c = q & 7;
            const __nv_bfloat16* src;
            if      (sel == 0) src = xh + (size_t)(m0 + r) * K + k0 + c * 8;
            else if (sel == 1) src = xl + (size_t)(m0 + r) * K + k0 + c * 8;
            else if (sel == 2) src = wh + (size_t)(n0 + r) * K + k0 + c * 8;
            else               src = wl + (size_t)(n0 + r) * K + k0 + c * 8;
            const uint32_t dst = base + sel * 16384 + r * 128 + (((uint32_t)(c ^ (r & 7))) << 4);
            asm volatile("cp.async.cg.shared.global [%0], [%1], 16;" :: "r"(dst), "l"(src));
        }
        asm volatile("cp.async.commit_group;");
    };

    int rA[2], cAx = lane >> 4;
#pragma unroll
    for (int s = 0; s < 2; s++)
        rA[s] = wm * 32 + s * 16 + (lane & 7) + ((lane >> 3) & 1) * 8;
    int rB[4], cBx = (lane >> 3) & 1;
#pragma unroll
    for (int jj = 0; jj < 4; jj++)
        rB[jj] = wn * 64 + (jj * 2 + (lane >> 4)) * 8 + (lane & 7);

    float acc[2][8][4];
#pragma unroll
    for (int s = 0; s < 2; s++)
#pragma unroll
        for (int j = 0; j < 8; j++)
#pragma unroll
            for (int v = 0; v < 4; v++) acc[s][j][v] = 0.f;

    stage(0);
#pragma unroll 1
    for (int kt = 0; kt < KT; kt++) {
        if (kt + 1 < KT) { stage(kt + 1); asm volatile("cp.async.wait_group 1;"); }
        else             { asm volatile("cp.async.wait_group 0;"); }
        __syncthreads();
        const uint32_t base = sbase + (kt & 1) * 65536;
        const uint32_t bXh = base, bXl = base + 16384, bWh = base + 32768, bWl = base + 49152;
#pragma unroll
        for (int ks = 0; ks < 4; ks++) {
            uint32_t ah[2][4], al[2][4], bh[4][4], bl[4][4];
#pragma unroll
            for (int s = 0; s < 2; s++) {
                const uint32_t off = rA[s] * 128 + (((uint32_t)((ks * 2 + cAx) ^ (rA[s] & 7))) << 4);
                asm volatile("ldmatrix.sync.aligned.m8n8.x4.shared.b16 {%0,%1,%2,%3}, [%4];"
                    : "=r"(ah[s][0]), "=r"(ah[s][1]), "=r"(ah[s][2]), "=r"(ah[s][3]) : "r"(bXh + off));
                asm volatile("ldmatrix.sync.aligned.m8n8.x4.shared.b16 {%0,%1,%2,%3}, [%4];"
                    : "=r"(al[s][0]), "=r"(al[s][1]), "=r"(al[s][2]), "=r"(al[s][3]) : "r"(bXl + off));
            }
#pragma unroll
            for (int jj = 0; jj < 4; jj++) {
                const uint32_t off = rB[jj] * 128 + (((uint32_t)((ks * 2 + cBx) ^ (rB[jj] & 7))) << 4);
                asm volatile("ldmatrix.sync.aligned.m8n8.x4.shared.b16 {%0,%1,%2,%3}, [%4];"
                    : "=r"(bh[jj][0]), "=r"(bh[jj][1]), "=r"(bh[jj][2]), "=r"(bh[jj][3]) : "r"(bWh + off));
                asm volatile("ldmatrix.sync.aligned.m8n8.x4.shared.b16 {%0,%1,%2,%3}, [%4];"
                    : "=r"(bl[jj][0]), "=r"(bl[jj][1]), "=r"(bl[jj][2]), "=r"(bl[jj][3]) : "r"(bWl + off));
            }
#pragma unroll
            for (int s = 0; s < 2; s++)
#pragma unroll
                for (int j = 0; j < 8; j++) {
                    float* cc = acc[s][j];
                    const uint32_t* fh = &bh[j >> 1][(j & 1) * 2];
                    const uint32_t* fl = &bl[j >> 1][(j & 1) * 2];
#define MMA_(A, Bf) asm volatile( \
    "mma.sync.aligned.m16n8k16.row.col.f32.bf16.bf16.f32 " \
    "{%0,%1,%2,%3}, {%4,%5,%6,%7}, {%8,%9}, {%0,%1,%2,%3};" \
    : "+f"(cc[0]), "+f"(cc[1]), "+f"(cc[2]), "+f"(cc[3]) \
    : "r"((A)[0]), "r"((A)[1]), "r"((A)[2]), "r"((A)[3]), "r"((Bf)[0]), "r"((Bf)[1]))
                    MMA_(ah[s], fh);
                    MMA_(al[s], fh);
                    MMA_(ah[s], fl);
#undef MMA_
                }
        }
        __syncthreads();
    }

    // ---- epilogue: store y + fused column stat partials ----
#pragma unroll
    for (int s = 0; s < 2; s++) {
        const int m = m0 + wm * 32 + s * 16 + (lane >> 2);
#pragma unroll
        for (int j = 0; j < 8; j++) {
            const int n = n0 + wn * 64 + j * 8 + (lane & 3) * 2;
            *(float2*)(C + (size_t)m * CO + n)       = make_float2(acc[s][j][0], acc[s][j][1]);
            *(float2*)(C + (size_t)(m + 8) * CO + n) = make_float2(acc[s][j][2], acc[s][j][3]);
        }
    }
    float sa[16], qa[16];
#pragma unroll
    for (int j = 0; j < 8; j++)
#pragma unroll
        for (int v = 0; v < 2; v++) {
            const float y0 = acc[0][j][v], y1 = acc[0][j][v + 2];
            const float y2 = acc[1][j][v], y3 = acc[1][j][v + 2];
            sa[j * 2 + v] = (y0 + y1) + (y2 + y3);
            qa[j * 2 + v] = fmaf(y0, y0, fmaf(y1, y1, fmaf(y2, y2, y3 * y3)));
        }
#pragma unroll
    for (int off = 4; off <= 16; off <<= 1)
#pragma unroll
        for (int u = 0; u < 16; u++) {
            sa[u] += __shfl_xor_sync(0xffffffffu, sa[u], off);
            qa[u] += __shfl_xor_sync(0xffffffffu, qa[u], off);
        }
    if (lane < 4) {
#pragma unroll
        for (int j = 0; j < 8; j++)
#pragma unroll
            for (int v = 0; v < 2; v++) {
                const int c = wn * 64 + j * 8 + lane * 2 + v;
                sm_s[wm][c] = sa[j * 2 + v];
                sm_q[wm][c] = qa[j * 2 + v];
            }
    }
    __syncthreads();
    if (tid < 128) {
        const int c = tid;
        g_psum[(size_t)(n0 + c) * 512 + blockIdx.x] =
            (sm_s[0][c] + sm_s[1][c]) + (sm_s[2][c] + sm_s[3][c]);
    } else {
        const int c = tid - 128;
        g_psq[(size_t)(n0 + c) * 512 + blockIdx.x] =
            (sm_q[0][c] + sm_q[1][c]) + (sm_q[2][c] + sm_q[3][c]);
    }
}

// ---------------------------------------------------------------------------
// fold: reduce 512 partials/channel -> folded BN affine
// ---------------------------------------------------------------------------
__global__ void k_fold(const float* __restrict__ gamma, const float* __restrict__ beta,
                       int layer) {
    const int c = threadIdx.x;
    float s = 0.f, q = 0.f;
    for (int j = 0; j < 512; j++) {
        s += g_psum[(size_t)c * 512 + j];
        q += g_psq[(size_t)c * 512 + j];
    }
    const float mean = s * (1.f / (float)NS);
    const float var  = q * (1.f / (float)NS) - mean * mean;
    const float a = gamma[c] * rsqrtf(var + 1e-5f);
    const float b = beta[c] - mean * a;
    if (layer == 1) { g_a1[c] = a; g_b1[c] = b; }
    else            { g_a2[c] = a; g_b2[c] = b; }
}

// ---------------------------------------------------------------------------
// x2 = split(relu(a1*y1 + b1))
// ---------------------------------------------------------------------------
__global__ void __launch_bounds__(256) k_x2() {
    const size_t i = (size_t)blockIdx.x * 256 + threadIdx.x;
    const size_t row = i >> 6;
    const int cq = (int)(i & 63), c0 = cq * 4;
    float4 v = ((const float4*)g_y1)[row * 64 + cq];
    const float4 a = *(const float4*)&g_a1[c0];
    const float4 b = *(const float4*)&g_b1[c0];
    v.x = fmaxf(fmaf(a.x, v.x, b.x), 0.f);
    v.y = fmaxf(fmaf(a.y, v.y, b.y), 0.f);
    v.z = fmaxf(fmaf(a.z, v.z, b.z), 0.f);
    v.w = fmaxf(fmaf(a.w, v.w, b.w), 0.f);
    uint32_t h0, l0, h1, l1, h2, l2, h3, l3;
    split_bf16(v.x, h0, l0); split_bf16(v.y, h1, l1);
    split_bf16(v.z, h2, l2); split_bf16(v.w, h3, l3);
    const size_t o = row * CO + c0;
    *(uint2*)(g_x2h + o) = make_uint2(h0 | (h1 << 16), h2 | (h3 << 16));
    *(uint2*)(g_x2l + o) = make_uint2(l0 | (l1 << 16), l2 | (l3 << 16));
}

// ---------------------------------------------------------------------------
// finalize: out[b,o,n] = relu(a2*y2[n,o] + b2)
// ---------------------------------------------------------------------------
__global__ void k_finalize(float* __restrict__ out) {
    __shared__ float t[32][33];
    const int b = blockIdx.z, o0 = blockIdx.y * 32, n0 = blockIdx.x * 32;
    const int tx = threadIdx.x, ty = threadIdx.y;
    const float a = g_a2[o0 + tx], bb = g_b2[o0 + tx];
#pragma unroll
    for (int i = 0; i < 4; i++) {
        const int n = n0 + ty + i * 8;
        const float v = g_y1[(size_t)(b * NPT + n) * CO + o0 + tx];
        t[tx][ty + i * 8] = fmaxf(fmaf(a, v, bb), 0.f);
    }
    __syncthreads();
#pragma unroll
    for (int i = 0; i < 4; i++)
        out[((size_t)b * CO + o0 + ty + i * 8) * NPT + n0 + tx] = t[ty + i * 8][tx];
}

// ---------------------------------------------------------------------------
// Launch
// ---------------------------------------------------------------------------
extern "C" void kernel_launch(void* const* d_in, const int* in_sizes, int n_in,
                              void* d_out, int out_size) {
    const float* xyz1    = (const float*)d_in[0];
    const float* xyz2    = (const float*)d_in[1];
    const float* points1 = (const float*)d_in[2];
    const float* points2 = (const float*)d_in[3];
    const float* W1      = (const float*)d_in[4];
    const float* g1      = (const float*)d_in[6];
    const float* be1     = (const float*)d_in[7];
    const float* W2      = (const float*)d_in[8];
    const float* g2      = (const float*)d_in[10];
    const float* be2     = (const float*)d_in[11];
    float* out = (float*)d_out;

    cudaFuncSetAttribute(k_mma<1>, cudaFuncAttributeMaxDynamicSharedMemorySize, MMA_SMEM);
    cudaFuncSetAttribute(k_mma<2>, cudaFuncAttributeMaxDynamicSharedMemorySize, MMA_SMEM);

    k_wsplit<<<640, 256>>>(W1, W2);
    k_tp2<<<dim3(32, 4, 16), dim3(32, 8)>>>(points2);
    k_tp1<<<dim3(128, 8, 16), dim3(32, 8)>>>(points1);
    k_nn<<<dim3(16, 16), 256>>>(xyz1, xyz2);
    k_gather<<<8192, 256>>>();
    k_mma<1><<<dim3(512, 2), 256, MMA_SMEM>>>();
    k_fold<<<1, 256>>>(g1, be1, 1);
    k_x2<<<16384, 256>>>();
    k_mma<2><<<dim3(512, 2), 256, MMA_SMEM>>>();
    k_fold<<<1, 256>>>(g2, be2, 2);
    k_finalize<<<dim3(128, 8, 16), dim3(32, 8)>>>(out);
}

// round 8
// speedup vs baseline: 1.6927x; 1.6927x over previous
#include <cuda_runtime.h>
#include <cuda_bf16.h>
#include <cstdint>
#include <cstddef>

#define B_   16
#define NPT  4096
#define SPT  1024
#define D1_  256
#define D2_  128
#define CIN  384
#define CO   256
#define NS   (B_*NPT)   // 65536

// ---------------------------------------------------------------------------
// Scratch
// ---------------------------------------------------------------------------
__device__ float         g_p2t[B_ * SPT * D2_];
__device__ __nv_bfloat16 g_x1h[(size_t)NS * CIN];
__device__ __nv_bfloat16 g_x1l[(size_t)NS * CIN];
__device__ __nv_bfloat16 g_x2h[(size_t)NS * CO];
__device__ __nv_bfloat16 g_x2l[(size_t)NS * CO];
__device__ float         g_y1[(size_t)NS * CO];     // y1, then reused as y2
__device__ __nv_bfloat16 g_w1h[CO * CIN], g_w1l[CO * CIN];
__device__ __nv_bfloat16 g_w2h[CO * CO],  g_w2l[CO * CO];
__device__ float g_psum[256 * 256], g_psq[256 * 256]; // [rowblock][channel] partials
__device__ float g_a1[CO], g_b1[CO], g_a2[CO], g_b2[CO];
__device__ float4 g_nnw4[NS];   // 3 normalized weights per query
__device__ int4   g_nni4[NS];   // 3 neighbor indices per query

__device__ __forceinline__ uint32_t smem_u32(const void* p) {
    uint32_t a;
    asm("{ .reg .u64 t; cvta.to.shared.u64 t, %1; cvt.u32.u64 %0, t; }" : "=r"(a) : "l"(p));
    return a;
}
__device__ __forceinline__ void split_bf16(float a, uint32_t& h, uint32_t& l) {
    __nv_bfloat16 hb = __float2bfloat16(a);
    __nv_bfloat16 lb = __float2bfloat16(a - __bfloat162float(hb));
    h = (uint32_t)__bfloat16_as_ushort(hb);
    l = (uint32_t)__bfloat16_as_ushort(lb);
}

// ---------------------------------------------------------------------------
// W split
// ---------------------------------------------------------------------------
__global__ void k_wsplit(const float* __restrict__ W1, const float* __restrict__ W2) {
    const int i = blockIdx.x * 256 + threadIdx.x;
    uint32_t h, l;
    if (i < CO * CIN) {
        split_bf16(W1[i], h, l);
        g_w1h[i] = __ushort_as_bfloat16((unsigned short)h);
        g_w1l[i] = __ushort_as_bfloat16((unsigned short)l);
    } else {
        const int j = i - CO * CIN;
        split_bf16(W2[j], h, l);
        g_w2h[j] = __ushort_as_bfloat16((unsigned short)h);
        g_w2l[j] = __ushort_as_bfloat16((unsigned short)l);
    }
}

// ---------------------------------------------------------------------------
// transpose points2 [B,D2,S] -> g_p2t [B,S,D2]
// ---------------------------------------------------------------------------
__global__ void k_tp2(const float* __restrict__ p2) {
    __shared__ float t[32][33];
    const int b = blockIdx.z, c0 = blockIdx.y * 32, s0 = blockIdx.x * 32;
    const int tx = threadIdx.x, ty = threadIdx.y;
#pragma unroll
    for (int i = 0; i < 4; i++)
        t[ty + i * 8][tx] = p2[((size_t)b * D2_ + c0 + ty + i * 8) * SPT + s0 + tx];
    __syncthreads();
#pragma unroll
    for (int i = 0; i < 4; i++)
        g_p2t[((size_t)b * SPT + s0 + ty + i * 8) * D2_ + c0 + tx] = t[tx][ty + i * 8];
}

// ---------------------------------------------------------------------------
// transpose+split points1 [B,256,N] -> X1 cols [0,256)
// ---------------------------------------------------------------------------
__global__ void k_tp1(const float* __restrict__ p1) {
    __shared__ float t[32][33];
    const int b = blockIdx.z, c0 = blockIdx.y * 32, n0 = blockIdx.x * 32;
    const int tx = threadIdx.x, ty = threadIdx.y;
    const int tid = ty * 32 + tx;
#pragma unroll
    for (int i = 0; i < 4; i++)
        t[ty + i * 8][tx] = p1[((size_t)b * D1_ + c0 + ty + i * 8) * NPT + n0 + tx];
    __syncthreads();
#pragma unroll
    for (int w = 0; w < 2; w++) {
        const int v = w * 256 + tid;
        const int n = v >> 4, u = v & 15;
        uint32_t h0, l0, h1, l1;
        split_bf16(t[2 * u][n], h0, l0);
        split_bf16(t[2 * u + 1][n], h1, l1);
        const size_t a = (size_t)(b * NPT + n0 + n) * CIN + c0 + 2 * u;
        *(uint32_t*)(g_x1h + a) = h0 | (h1 << 16);
        *(uint32_t*)(g_x1l + a) = l0 | (l1 << 16);
    }
}

// ---------------------------------------------------------------------------
// k_nn: 3-NN with RARE-BRANCH insertion. Common path per point:
// LDS.128 + 3 FMA + 1 FSETP + branch. Insertion chain only when d < d2
// (expected ~320/1024 warp-divergent iterations).
// ---------------------------------------------------------------------------
__global__ void __launch_bounds__(256) k_nn(const float* __restrict__ xyz1,
                                            const float* __restrict__ xyz2) {
    __shared__ float4 s2[SPT];
    const int b = blockIdx.y, tid = threadIdx.x;
    const int n = blockIdx.x * 256 + tid;
    for (int i = tid; i < SPT; i += 256) {
        const float x = xyz2[(size_t)b * 3072 + i];
        const float y = xyz2[(size_t)b * 3072 + 1024 + i];
        const float z = xyz2[(size_t)b * 3072 + 2048 + i];
        s2[i] = make_float4(x, y, z, fmaf(x, x, fmaf(y, y, z * z)));
    }
    __syncthreads();

    const float px = xyz1[((size_t)b * 3 + 0) * NPT + n];
    const float py = xyz1[((size_t)b * 3 + 1) * NPT + n];
    const float pz = xyz1[((size_t)b * 3 + 2) * NPT + n];
    const float mx = -2.f * px, my = -2.f * py, mz = -2.f * pz;
    const float a2 = fmaf(px, px, fmaf(py, py, pz * pz));

    float d0 = 1e30f, d1 = 1e30f, d2 = 1e30f;
    int   i0 = 0, i1 = 0, i2 = 0;
#pragma unroll 4
    for (int s = 0; s < SPT; s++) {
        const float4 v = s2[s];
        const float d = fmaf(mx, v.x, fmaf(my, v.y, fmaf(mz, v.z, v.w)));
        if (d < d2) {
            const bool p0 = d < d0, p1 = d < d1;
            i2 = p1 ? i1 : s;
            d2 = p1 ? d1 : d;
            i1 = p0 ? i0 : (p1 ? s : i1);
            d1 = p0 ? d0 : (p1 ? d : d1);
            i0 = p0 ? s : i0;
            d0 = p0 ? d : d0;
        }
    }
    const float f0 = sqrtf(fmaxf(d0 + a2, 0.f));
    const float f1 = sqrtf(fmaxf(d1 + a2, 0.f));
    const float f2 = sqrtf(fmaxf(d2 + a2, 0.f));
    float w0 = 1.f / (f0 + 1e-10f);
    float w1 = 1.f / (f1 + 1e-10f);
    float w2 = 1.f / (f2 + 1e-10f);
    const float inv = 1.f / (w0 + w1 + w2);
    const int q = b * NPT + n;
    g_nnw4[q] = make_float4(w0 * inv, w1 * inv, w2 * inv, 0.f);
    g_nni4[q] = make_int4(i0, i1, i2, 0);
}

// ---------------------------------------------------------------------------
// k_gather: warp per query; register accumulation; bf16 hi/lo out (X1 cols
// [256,384)). Rows of g_p2t are 512B contiguous -> coalesced per warp.
// ---------------------------------------------------------------------------
__global__ void __launch_bounds__(256) k_gather() {
    const int wid = threadIdx.x >> 5, lane = threadIdx.x & 31;
    const int n = blockIdx.x * 8 + wid;           // global query id
    const int b = n >> 12;
    const float4 wv = g_nnw4[n];
    const int4   iv = g_nni4[n];
    const float* p2t = g_p2t + (size_t)b * SPT * D2_;
    const float4 v0 = *(const float4*)(p2t + (size_t)iv.x * D2_ + lane * 4);
    const float4 v1 = *(const float4*)(p2t + (size_t)iv.y * D2_ + lane * 4);
    const float4 v2 = *(const float4*)(p2t + (size_t)iv.z * D2_ + lane * 4);
    float4 a;
    a.x = fmaf(wv.x, v0.x, fmaf(wv.y, v1.x, wv.z * v2.x));
    a.y = fmaf(wv.x, v0.y, fmaf(wv.y, v1.y, wv.z * v2.y));
    a.z = fmaf(wv.x, v0.z, fmaf(wv.y, v1.z, wv.z * v2.z));
    a.w = fmaf(wv.x, v0.w, fmaf(wv.y, v1.w, wv.z * v2.w));
    uint32_t h0, l0, h1, l1, h2, l2, h3, l3;
    split_bf16(a.x, h0, l0); split_bf16(a.y, h1, l1);
    split_bf16(a.z, h2, l2); split_bf16(a.w, h3, l3);
    const size_t o = (size_t)n * CIN + D1_ + lane * 4;
    *(uint2*)(g_x1h + o) = make_uint2(h0 | (h1 << 16), h2 | (h3 << 16));
    *(uint2*)(g_x1l + o) = make_uint2(l0 | (l1 << 16), l2 | (l3 << 16));
}

// ---------------------------------------------------------------------------
// Warp-MMA GEMM (lean epilogue — stats moved back to k_stats).
// C[n,256] = X[n,K] * W[256,K]^T ; CTA 128x128, K-chunk 64, cp.async double
// buffer, 8 warps 4(M)x2(N).
// ---------------------------------------------------------------------------
#define MMA_SMEM (2 * 65536 + 1024)

template <int LAYER>
__global__ void __launch_bounds__(256) k_mma() {
    constexpr int K  = (LAYER == 1) ? CIN : CO;
    constexpr int KT = K / 64;
    const __nv_bfloat16* xh = (LAYER == 1) ? g_x1h : g_x2h;
    const __nv_bfloat16* xl = (LAYER == 1) ? g_x1l : g_x2l;
    const __nv_bfloat16* wh = (LAYER == 1) ? g_w1h : g_w2h;
    const __nv_bfloat16* wl = (LAYER == 1) ? g_w1l : g_w2l;
    float* C = g_y1;

    extern __shared__ uint8_t dsm[];
    const uint32_t sbase = (smem_u32(dsm) + 1023) & ~1023u;

    const int tid  = threadIdx.x, wid = tid >> 5, lane = tid & 31;
    const int m0   = blockIdx.x << 7;
    const int n0   = blockIdx.y << 7;
    const int wm   = wid & 3, wn = wid >> 2;

    auto stage = [&](int kt) {
        const int buf = kt & 1;
        const uint32_t base = sbase + buf * 65536;
        const int k0 = kt * 64;
#pragma unroll
        for (int i = 0; i < 16; i++) {
            const int q = tid + i * 256;
            const int sel = q >> 10;
            const int r = (q & 1023) >> 3, c = q & 7;
            const __nv_bfloat16* src;
            if      (sel == 0) src = xh + (size_t)(m0 + r) * K + k0 + c * 8;
            else if (sel == 1) src = xl + (size_t)(m0 + r) * K + k0 + c * 8;
            else if (sel == 2) src = wh + (size_t)(n0 + r) * K + k0 + c * 8;
            else               src = wl + (size_t)(n0 + r) * K + k0 + c * 8;
            const uint32_t dst = base + sel * 16384 + r * 128 + (((uint32_t)(c ^ (r & 7))) << 4);
            asm volatile("cp.async.cg.shared.global [%0], [%1], 16;" :: "r"(dst), "l"(src));
        }
        asm volatile("cp.async.commit_group;");
    };

    int rA[2], cAx = lane >> 4;
#pragma unroll
    for (int s = 0; s < 2; s++)
        rA[s] = wm * 32 + s * 16 + (lane & 7) + ((lane >> 3) & 1) * 8;
    int rB[4], cBx = (lane >> 3) & 1;
#pragma unroll
    for (int jj = 0; jj < 4; jj++)
        rB[jj] = wn * 64 + (jj * 2 + (lane >> 4)) * 8 + (lane & 7);

    float acc[2][8][4];
#pragma unroll
    for (int s = 0; s < 2; s++)
#pragma unroll
        for (int j = 0; j < 8; j++)
#pragma unroll
            for (int v = 0; v < 4; v++) acc[s][j][v] = 0.f;

    stage(0);
#pragma unroll 1
    for (int kt = 0; kt < KT; kt++) {
        if (kt + 1 < KT) { stage(kt + 1); asm volatile("cp.async.wait_group 1;"); }
        else             { asm volatile("cp.async.wait_group 0;"); }
        __syncthreads();
        const uint32_t base = sbase + (kt & 1) * 65536;
        const uint32_t bXh = base, bXl = base + 16384, bWh = base + 32768, bWl = base + 49152;
#pragma unroll
        for (int ks = 0; ks < 4; ks++) {
            uint32_t ah[2][4], al[2][4], bh[4][4], bl[4][4];
#pragma unroll
            for (int s = 0; s < 2; s++) {
                const uint32_t off = rA[s] * 128 + (((uint32_t)((ks * 2 + cAx) ^ (rA[s] & 7))) << 4);
                asm volatile("ldmatrix.sync.aligned.m8n8.x4.shared.b16 {%0,%1,%2,%3}, [%4];"
                    : "=r"(ah[s][0]), "=r"(ah[s][1]), "=r"(ah[s][2]), "=r"(ah[s][3]) : "r"(bXh + off));
                asm volatile("ldmatrix.sync.aligned.m8n8.x4.shared.b16 {%0,%1,%2,%3}, [%4];"
                    : "=r"(al[s][0]), "=r"(al[s][1]), "=r"(al[s][2]), "=r"(al[s][3]) : "r"(bXl + off));
            }
#pragma unroll
            for (int jj = 0; jj < 4; jj++) {
                const uint32_t off = rB[jj] * 128 + (((uint32_t)((ks * 2 + cBx) ^ (rB[jj] & 7))) << 4);
                asm volatile("ldmatrix.sync.aligned.m8n8.x4.shared.b16 {%0,%1,%2,%3}, [%4];"
                    : "=r"(bh[jj][0]), "=r"(bh[jj][1]), "=r"(bh[jj][2]), "=r"(bh[jj][3]) : "r"(bWh + off));
                asm volatile("ldmatrix.sync.aligned.m8n8.x4.shared.b16 {%0,%1,%2,%3}, [%4];"
                    : "=r"(bl[jj][0]), "=r"(bl[jj][1]), "=r"(bl[jj][2]), "=r"(bl[jj][3]) : "r"(bWl + off));
            }
#pragma unroll
            for (int s = 0; s < 2; s++)
#pragma unroll
                for (int j = 0; j < 8; j++) {
                    float* cc = acc[s][j];
                    const uint32_t* fh = &bh[j >> 1][(j & 1) * 2];
                    const uint32_t* fl = &bl[j >> 1][(j & 1) * 2];
#define MMA_(A, Bf) asm volatile( \
    "mma.sync.aligned.m16n8k16.row.col.f32.bf16.bf16.f32 " \
    "{%0,%1,%2,%3}, {%4,%5,%6,%7}, {%8,%9}, {%0,%1,%2,%3};" \
    : "+f"(cc[0]), "+f"(cc[1]), "+f"(cc[2]), "+f"(cc[3]) \
    : "r"((A)[0]), "r"((A)[1]), "r"((A)[2]), "r"((A)[3]), "r"((Bf)[0]), "r"((Bf)[1]))
                    MMA_(ah[s], fh);
                    MMA_(al[s], fh);
                    MMA_(ah[s], fl);
#undef MMA_
                }
        }
        __syncthreads();
    }

    // ---- lean epilogue: direct fp32 stores to C[n,256] ----
#pragma unroll
    for (int s = 0; s < 2; s++) {
        const int m = m0 + wm * 32 + s * 16 + (lane >> 2);
#pragma unroll
        for (int j = 0; j < 8; j++) {
            const int n = n0 + wn * 64 + j * 8 + (lane & 3) * 2;
            *(float2*)(C + (size_t)m * CO + n)       = make_float2(acc[s][j][0], acc[s][j][1]);
            *(float2*)(C + (size_t)(m + 8) * CO + n) = make_float2(acc[s][j][2], acc[s][j][3]);
        }
    }
}

// ---------------------------------------------------------------------------
// k_stats: per-channel partial sums over y [n,256] (coalesced float4 reads),
// deterministic per-rowblock partials in g_psum/g_psq[j*256 + c].
// ---------------------------------------------------------------------------
__global__ void __launch_bounds__(256) k_stats() {
    __shared__ float4 ss[256], qq[256];
    const int j = blockIdx.x, t = threadIdx.x;
    const int cq = t & 63, rq = t >> 6;
    const float4* y = (const float4*)g_y1;
    float4 s = make_float4(0, 0, 0, 0), q = make_float4(0, 0, 0, 0);
    for (int i = 0; i < 64; i++) {
        const int row = j * 256 + rq * 64 + i;
        const float4 v = y[(size_t)row * 64 + cq];
        s.x += v.x; s.y += v.y; s.z += v.z; s.w += v.w;
        q.x = fmaf(v.x, v.x, q.x); q.y = fmaf(v.y, v.y, q.y);
        q.z = fmaf(v.z, v.z, q.z); q.w = fmaf(v.w, v.w, q.w);
    }
    ss[t] = s; qq[t] = q;
    __syncthreads();
    if (t < 64) {
        float4 a = ss[t], b = ss[t + 64], c = ss[t + 128], d = ss[t + 192];
        float4 e = qq[t], f = qq[t + 64], g = qq[t + 128], h = qq[t + 192];
        float4 so = make_float4((a.x + b.x) + (c.x + d.x), (a.y + b.y) + (c.y + d.y),
                                (a.z + b.z) + (c.z + d.z), (a.w + b.w) + (c.w + d.w));
        float4 qo = make_float4((e.x + f.x) + (g.x + h.x), (e.y + f.y) + (g.y + h.y),
                                (e.z + f.z) + (g.z + h.z), (e.w + f.w) + (g.w + h.w));
        *(float4*)&g_psum[j * 256 + t * 4] = so;
        *(float4*)&g_psq[j * 256 + t * 4]  = qo;
    }
}

// ---------------------------------------------------------------------------
// fold: reduce 256 partials/channel -> folded BN affine
// ---------------------------------------------------------------------------
__global__ void k_fold(const float* __restrict__ gamma, const float* __restrict__ beta,
                       int layer) {
    const int c = threadIdx.x;
    float s = 0.f, q = 0.f;
    for (int j = 0; j < 256; j++) {
        s += g_psum[j * 256 + c];
        q += g_psq[j * 256 + c];
    }
    const float mean = s * (1.f / (float)NS);
    const float var  = q * (1.f / (float)NS) - mean * mean;
    const float a = gamma[c] * rsqrtf(var + 1e-5f);
    const float b = beta[c] - mean * a;
    if (layer == 1) { g_a1[c] = a; g_b1[c] = b; }
    else            { g_a2[c] = a; g_b2[c] = b; }
}

// ---------------------------------------------------------------------------
// x2 = split(relu(a1*y1 + b1))
// ---------------------------------------------------------------------------
__global__ void __launch_bounds__(256) k_x2() {
    const size_t i = (size_t)blockIdx.x * 256 + threadIdx.x;
    const size_t row = i >> 6;
    const int cq = (int)(i & 63), c0 = cq * 4;
    float4 v = ((const float4*)g_y1)[row * 64 + cq];
    const float4 a = *(const float4*)&g_a1[c0];
    const float4 b = *(const float4*)&g_b1[c0];
    v.x = fmaxf(fmaf(a.x, v.x, b.x), 0.f);
    v.y = fmaxf(fmaf(a.y, v.y, b.y), 0.f);
    v.z = fmaxf(fmaf(a.z, v.z, b.z), 0.f);
    v.w = fmaxf(fmaf(a.w, v.w, b.w), 0.f);
    uint32_t h0, l0, h1, l1, h2, l2, h3, l3;
    split_bf16(v.x, h0, l0); split_bf16(v.y, h1, l1);
    split_bf16(v.z, h2, l2); split_bf16(v.w, h3, l3);
    const size_t o = row * CO + c0;
    *(uint2*)(g_x2h + o) = make_uint2(h0 | (h1 << 16), h2 | (h3 << 16));
    *(uint2*)(g_x2l + o) = make_uint2(l0 | (l1 << 16), l2 | (l3 << 16));
}

// ---------------------------------------------------------------------------
// finalize: out[b,o,n] = relu(a2*y2[n,o] + b2)
// ---------------------------------------------------------------------------
__global__ void k_finalize(float* __restrict__ out) {
    __shared__ float t[32][33];
    const int b = blockIdx.z, o0 = blockIdx.y * 32, n0 = blockIdx.x * 32;
    const int tx = threadIdx.x, ty = threadIdx.y;
    const float a = g_a2[o0 + tx], bb = g_b2[o0 + tx];
#pragma unroll
    for (int i = 0; i < 4; i++) {
        const int n = n0 + ty + i * 8;
        const float v = g_y1[(size_t)(b * NPT + n) * CO + o0 + tx];
        t[tx][ty + i * 8] = fmaxf(fmaf(a, v, bb), 0.f);
    }
    __syncthreads();
#pragma unroll
    for (int i = 0; i < 4; i++)
        out[((size_t)b * CO + o0 + ty + i * 8) * NPT + n0 + tx] = t[ty + i * 8][tx];
}

// ---------------------------------------------------------------------------
// Launch
// ---------------------------------------------------------------------------
extern "C" void kernel_launch(void* const* d_in, const int* in_sizes, int n_in,
                              void* d_out, int out_size) {
    const float* xyz1    = (const float*)d_in[0];
    const float* xyz2    = (const float*)d_in[1];
    const float* points1 = (const float*)d_in[2];
    const float* points2 = (const float*)d_in[3];
    const float* W1      = (const float*)d_in[4];
    const float* g1      = (const float*)d_in[6];
    const float* be1     = (const float*)d_in[7];
    const float* W2      = (const float*)d_in[8];
    const float* g2      = (const float*)d_in[10];
    const float* be2     = (const float*)d_in[11];
    float* out = (float*)d_out;

    cudaFuncSetAttribute(k_mma<1>, cudaFuncAttributeMaxDynamicSharedMemorySize, MMA_SMEM);
    cudaFuncSetAttribute(k_mma<2>, cudaFuncAttributeMaxDynamicSharedMemorySize, MMA_SMEM);

    k_wsplit<<<640, 256>>>(W1, W2);
    k_tp2<<<dim3(32, 4, 16), dim3(32, 8)>>>(points2);
    k_tp1<<<dim3(128, 8, 16), dim3(32, 8)>>>(points1);
    k_nn<<<dim3(16, 16), 256>>>(xyz1, xyz2);
    k_gather<<<8192, 256>>>();
    k_mma<1><<<dim3(512, 2), 256, MMA_SMEM>>>();
    k_stats<<<256, 256>>>();
    k_fold<<<1, 256>>>(g1, be1, 1);
    k_x2<<<16384, 256>>>();
    k_mma<2><<<dim3(512, 2), 256, MMA_SMEM>>>();
    k_stats<<<256, 256>>>();
    k_fold<<<1, 256>>>(g2, be2, 2);
    k_finalize<<<dim3(128, 8, 16), dim3(32, 8)>>>(out);
}

// round 9
// speedup vs baseline: 1.7206x; 1.0165x over previous
#include <cuda_runtime.h>
#include <cuda_bf16.h>
#include <cstdint>
#include <cstddef>

#define B_   16
#define NPT  4096
#define SPT  1024
#define D1_  256
#define D2_  128
#define CIN  384
#define CO   256
#define NS   (B_*NPT)   // 65536

// ---------------------------------------------------------------------------
// Scratch
// ---------------------------------------------------------------------------
__device__ float         g_p2t[B_ * SPT * D2_];
__device__ __nv_bfloat16 g_x1h[(size_t)NS * CIN];
__device__ __nv_bfloat16 g_x1l[(size_t)NS * CIN];
__device__ __nv_bfloat16 g_x2h[(size_t)NS * CO];
__device__ __nv_bfloat16 g_x2l[(size_t)NS * CO];
__device__ float         g_y1[(size_t)NS * CO];     // y1, then reused as y2
__device__ __nv_bfloat16 g_w1h[CO * CIN], g_w1l[CO * CIN];
__device__ __nv_bfloat16 g_w2h[CO * CO],  g_w2l[CO * CO];
__device__ float g_psum[256 * 256], g_psq[256 * 256]; // [rowblock][channel] partials
__device__ float g_a1[CO], g_b1[CO], g_a2[CO], g_b2[CO];
__device__ float4 g_nnw4[NS];   // 3 normalized weights per query
__device__ int4   g_nni4[NS];   // 3 neighbor indices per query

__device__ __forceinline__ uint32_t smem_u32(const void* p) {
    uint32_t a;
    asm("{ .reg .u64 t; cvta.to.shared.u64 t, %1; cvt.u32.u64 %0, t; }" : "=r"(a) : "l"(p));
    return a;
}
__device__ __forceinline__ void split_bf16(float a, uint32_t& h, uint32_t& l) {
    __nv_bfloat16 hb = __float2bfloat16(a);
    __nv_bfloat16 lb = __float2bfloat16(a - __bfloat162float(hb));
    h = (uint32_t)__bfloat16_as_ushort(hb);
    l = (uint32_t)__bfloat16_as_ushort(lb);
}

// ---------------------------------------------------------------------------
// W split
// ---------------------------------------------------------------------------
__global__ void k_wsplit(const float* __restrict__ W1, const float* __restrict__ W2) {
    const int i = blockIdx.x * 256 + threadIdx.x;
    uint32_t h, l;
    if (i < CO * CIN) {
        split_bf16(W1[i], h, l);
        g_w1h[i] = __ushort_as_bfloat16((unsigned short)h);
        g_w1l[i] = __ushort_as_bfloat16((unsigned short)l);
    } else {
        const int j = i - CO * CIN;
        split_bf16(W2[j], h, l);
        g_w2h[j] = __ushort_as_bfloat16((unsigned short)h);
        g_w2l[j] = __ushort_as_bfloat16((unsigned short)l);
    }
}

// ---------------------------------------------------------------------------
// transpose points2 [B,D2,S] -> g_p2t [B,S,D2]
// ---------------------------------------------------------------------------
__global__ void k_tp2(const float* __restrict__ p2) {
    __shared__ float t[32][33];
    const int b = blockIdx.z, c0 = blockIdx.y * 32, s0 = blockIdx.x * 32;
    const int tx = threadIdx.x, ty = threadIdx.y;
#pragma unroll
    for (int i = 0; i < 4; i++)
        t[ty + i * 8][tx] = p2[((size_t)b * D2_ + c0 + ty + i * 8) * SPT + s0 + tx];
    __syncthreads();
#pragma unroll
    for (int i = 0; i < 4; i++)
        g_p2t[((size_t)b * SPT + s0 + ty + i * 8) * D2_ + c0 + tx] = t[tx][ty + i * 8];
}

// ---------------------------------------------------------------------------
// transpose+split points1 [B,256,N] -> X1 cols [0,256)
// ---------------------------------------------------------------------------
__global__ void k_tp1(const float* __restrict__ p1) {
    __shared__ float t[32][33];
    const int b = blockIdx.z, c0 = blockIdx.y * 32, n0 = blockIdx.x * 32;
    const int tx = threadIdx.x, ty = threadIdx.y;
    const int tid = ty * 32 + tx;
#pragma unroll
    for (int i = 0; i < 4; i++)
        t[ty + i * 8][tx] = p1[((size_t)b * D1_ + c0 + ty + i * 8) * NPT + n0 + tx];
    __syncthreads();
#pragma unroll
    for (int w = 0; w < 2; w++) {
        const int v = w * 256 + tid;
        const int n = v >> 4, u = v & 15;
        uint32_t h0, l0, h1, l1;
        split_bf16(t[2 * u][n], h0, l0);
        split_bf16(t[2 * u + 1][n], h1, l1);
        const size_t a = (size_t)(b * NPT + n0 + n) * CIN + c0 + 2 * u;
        *(uint32_t*)(g_x1h + a) = h0 | (h1 << 16);
        *(uint32_t*)(g_x1l + a) = l0 | (l1 << 16);
    }
}

// ---------------------------------------------------------------------------
// k_nn: split-S 3-NN. 2 threads per query, each scans 512 of 1024 refs
// (rare-branch insertion), then the two sorted top-3 triples are merged
// through smem. Doubles occupancy and halves the serial loop vs R8.
// ---------------------------------------------------------------------------
__global__ void __launch_bounds__(256) k_nn(const float* __restrict__ xyz1,
                                            const float* __restrict__ xyz2) {
    __shared__ float4 s2[SPT];
    __shared__ float sd[3][128];
    __shared__ int   si[3][128];
    const int b = blockIdx.y, tid = threadIdx.x;
    const int q = tid & 127, half = tid >> 7;
    const int n = blockIdx.x * 128 + q;
    for (int i = tid; i < SPT; i += 256) {
        const float x = xyz2[(size_t)b * 3072 + i];
        const float y = xyz2[(size_t)b * 3072 + 1024 + i];
        const float z = xyz2[(size_t)b * 3072 + 2048 + i];
        s2[i] = make_float4(x, y, z, fmaf(x, x, fmaf(y, y, z * z)));
    }
    __syncthreads();

    const float px = xyz1[((size_t)b * 3 + 0) * NPT + n];
    const float py = xyz1[((size_t)b * 3 + 1) * NPT + n];
    const float pz = xyz1[((size_t)b * 3 + 2) * NPT + n];
    const float mx = -2.f * px, my = -2.f * py, mz = -2.f * pz;
    const float a2 = fmaf(px, px, fmaf(py, py, pz * pz));

    float d0 = 1e30f, d1 = 1e30f, d2 = 1e30f;
    int   i0 = 0, i1 = 0, i2 = 0;
    const int sbeg = half << 9;
#pragma unroll 4
    for (int s = sbeg; s < sbeg + 512; s++) {
        const float4 v = s2[s];
        const float d = fmaf(mx, v.x, fmaf(my, v.y, fmaf(mz, v.z, v.w)));
        if (d < d2) {
            const bool p0 = d < d0, p1 = d < d1;
            i2 = p1 ? i1 : s;
            d2 = p1 ? d1 : d;
            i1 = p0 ? i0 : (p1 ? s : i1);
            d1 = p0 ? d0 : (p1 ? d : d1);
            i0 = p0 ? s : i0;
            d0 = p0 ? d : d0;
        }
    }
    if (half) {
        sd[0][q] = d0; sd[1][q] = d1; sd[2][q] = d2;
        si[0][q] = i0; si[1][q] = i1; si[2][q] = i2;
    }
    __syncthreads();
    if (!half) {
        float b0 = sd[0][q], b1 = sd[1][q], b2 = sd[2][q];
        int   j0 = si[0][q], j1 = si[1][q], j2 = si[2][q];
        float m0, m1, m2; int o0, o1, o2;
        bool t = b0 < d0;                       // ties -> lower-index half (d)
        m0 = t ? b0 : d0; o0 = t ? j0 : i0;
        if (t) { b0 = b1; j0 = j1; b1 = b2; j1 = j2; }
        else   { d0 = d1; i0 = i1; d1 = d2; i1 = i2; }
        t = b0 < d0;
        m1 = t ? b0 : d0; o1 = t ? j0 : i0;
        if (t) { b0 = b1; j0 = j1; }
        else   { d0 = d1; i0 = i1; }
        t = b0 < d0;
        m2 = t ? b0 : d0; o2 = t ? j0 : i0;

        const float f0 = sqrtf(fmaxf(m0 + a2, 0.f));
        const float f1 = sqrtf(fmaxf(m1 + a2, 0.f));
        const float f2 = sqrtf(fmaxf(m2 + a2, 0.f));
        float w0 = 1.f / (f0 + 1e-10f);
        float w1 = 1.f / (f1 + 1e-10f);
        float w2 = 1.f / (f2 + 1e-10f);
        const float inv = 1.f / (w0 + w1 + w2);
        const int g = b * NPT + n;
        g_nnw4[g] = make_float4(w0 * inv, w1 * inv, w2 * inv, 0.f);
        g_nni4[g] = make_int4(o0, o1, o2, 0);
    }
}

// ---------------------------------------------------------------------------
// k_gather: warp per query; register accumulation; bf16 hi/lo out (X1 cols
// [256,384)). Rows of g_p2t are 512B contiguous -> coalesced per warp.
// ---------------------------------------------------------------------------
__global__ void __launch_bounds__(256) k_gather() {
    const int wid = threadIdx.x >> 5, lane = threadIdx.x & 31;
    const int n = blockIdx.x * 8 + wid;           // global query id
    const int b = n >> 12;
    const float4 wv = g_nnw4[n];
    const int4   iv = g_nni4[n];
    const float* p2t = g_p2t + (size_t)b * SPT * D2_;
    const float4 v0 = *(const float4*)(p2t + (size_t)iv.x * D2_ + lane * 4);
    const float4 v1 = *(const float4*)(p2t + (size_t)iv.y * D2_ + lane * 4);
    const float4 v2 = *(const float4*)(p2t + (size_t)iv.z * D2_ + lane * 4);
    float4 a;
    a.x = fmaf(wv.x, v0.x, fmaf(wv.y, v1.x, wv.z * v2.x));
    a.y = fmaf(wv.x, v0.y, fmaf(wv.y, v1.y, wv.z * v2.y));
    a.z = fmaf(wv.x, v0.z, fmaf(wv.y, v1.z, wv.z * v2.z));
    a.w = fmaf(wv.x, v0.w, fmaf(wv.y, v1.w, wv.z * v2.w));
    uint32_t h0, l0, h1, l1, h2, l2, h3, l3;
    split_bf16(a.x, h0, l0); split_bf16(a.y, h1, l1);
    split_bf16(a.z, h2, l2); split_bf16(a.w, h3, l3);
    const size_t o = (size_t)n * CIN + D1_ + lane * 4;
    *(uint2*)(g_x1h + o) = make_uint2(h0 | (h1 << 16), h2 | (h3 << 16));
    *(uint2*)(g_x1l + o) = make_uint2(l0 | (l1 << 16), l2 | (l3 << 16));
}

// ---------------------------------------------------------------------------
// Warp-MMA GEMM. C[n,256] = X[n,K] * W[256,K]^T ; CTA 128x128, K-chunk 64,
// cp.async double buffer, 8 warps 4(M)x2(N).
// Grid is (2, 512): the two CTAs sharing an X tile are ADJACENT in linear
// schedule order -> second X read hits L2 (halves X DRAM traffic).
// ---------------------------------------------------------------------------
#define MMA_SMEM (2 * 65536 + 1024)

template <int LAYER>
__global__ void __launch_bounds__(256) k_mma() {
    constexpr int K  = (LAYER == 1) ? CIN : CO;
    constexpr int KT = K / 64;
    const __nv_bfloat16* xh = (LAYER == 1) ? g_x1h : g_x2h;
    const __nv_bfloat16* xl = (LAYER == 1) ? g_x1l : g_x2l;
    const __nv_bfloat16* wh = (LAYER == 1) ? g_w1h : g_w2h;
    const __nv_bfloat16* wl = (LAYER == 1) ? g_w1l : g_w2l;
    float* C = g_y1;

    extern __shared__ uint8_t dsm[];
    const uint32_t sbase = (smem_u32(dsm) + 1023) & ~1023u;

    const int tid  = threadIdx.x, wid = tid >> 5, lane = tid & 31;
    const int m0   = blockIdx.y << 7;     // sample tile (slow axis)
    const int n0   = blockIdx.x << 7;     // channel tile (fast axis, pair shares X)
    const int wm   = wid & 3, wn = wid >> 2;

    auto stage = [&](int kt) {
        const int buf = kt & 1;
        const uint32_t base = sbase + buf * 65536;
        const int k0 = kt * 64;
#pragma unroll
        for (int i = 0; i < 16; i++) {
            const int q = tid + i * 256;
            const int sel = q >> 10;
            const int r = (q & 1023) >> 3, c = q & 7;
            const __nv_bfloat16* src;
            if      (sel == 0) src = xh + (size_t)(m0 + r) * K + k0 + c * 8;
            else if (sel == 1) src = xl + (size_t)(m0 + r) * K + k0 + c * 8;
            else if (sel == 2) src = wh + (size_t)(n0 + r) * K + k0 + c * 8;
            else               src = wl + (size_t)(n0 + r) * K + k0 + c * 8;
            const uint32_t dst = base + sel * 16384 + r * 128 + (((uint32_t)(c ^ (r & 7))) << 4);
            asm volatile("cp.async.cg.shared.global [%0], [%1], 16;" :: "r"(dst), "l"(src));
        }
        asm volatile("cp.async.commit_group;");
    };

    int rA[2], cAx = lane >> 4;
#pragma unroll
    for (int s = 0; s < 2; s++)
        rA[s] = wm * 32 + s * 16 + (lane & 7) + ((lane >> 3) & 1) * 8;
    int rB[4], cBx = (lane >> 3) & 1;
#pragma unroll
    for (int jj = 0; jj < 4; jj++)
        rB[jj] = wn * 64 + (jj * 2 + (lane >> 4)) * 8 + (lane & 7);

    float acc[2][8][4];
#pragma unroll
    for (int s = 0; s < 2; s++)
#pragma unroll
        for (int j = 0; j < 8; j++)
#pragma unroll
            for (int v = 0; v < 4; v++) acc[s][j][v] = 0.f;

    stage(0);
#pragma unroll 1
    for (int kt = 0; kt < KT; kt++) {
        if (kt + 1 < KT) { stage(kt + 1); asm volatile("cp.async.wait_group 1;"); }
        else             { asm volatile("cp.async.wait_group 0;"); }
        __syncthreads();
        const uint32_t base = sbase + (kt & 1) * 65536;
        const uint32_t bXh = base, bXl = base + 16384, bWh = base + 32768, bWl = base + 49152;
#pragma unroll
        for (int ks = 0; ks < 4; ks++) {
            uint32_t ah[2][4], al[2][4], bh[4][4], bl[4][4];
#pragma unroll
            for (int s = 0; s < 2; s++) {
                const uint32_t off = rA[s] * 128 + (((uint32_t)((ks * 2 + cAx) ^ (rA[s] & 7))) << 4);
                asm volatile("ldmatrix.sync.aligned.m8n8.x4.shared.b16 {%0,%1,%2,%3}, [%4];"
                    : "=r"(ah[s][0]), "=r"(ah[s][1]), "=r"(ah[s][2]), "=r"(ah[s][3]) : "r"(bXh + off));
                asm volatile("ldmatrix.sync.aligned.m8n8.x4.shared.b16 {%0,%1,%2,%3}, [%4];"
                    : "=r"(al[s][0]), "=r"(al[s][1]), "=r"(al[s][2]), "=r"(al[s][3]) : "r"(bXl + off));
            }
#pragma unroll
            for (int jj = 0; jj < 4; jj++) {
                const uint32_t off = rB[jj] * 128 + (((uint32_t)((ks * 2 + cBx) ^ (rB[jj] & 7))) << 4);
                asm volatile("ldmatrix.sync.aligned.m8n8.x4.shared.b16 {%0,%1,%2,%3}, [%4];"
                    : "=r"(bh[jj][0]), "=r"(bh[jj][1]), "=r"(bh[jj][2]), "=r"(bh[jj][3]) : "r"(bWh + off));
                asm volatile("ldmatrix.sync.aligned.m8n8.x4.shared.b16 {%0,%1,%2,%3}, [%4];"
                    : "=r"(bl[jj][0]), "=r"(bl[jj][1]), "=r"(bl[jj][2]), "=r"(bl[jj][3]) : "r"(bWl + off));
            }
#pragma unroll
            for (int s = 0; s < 2; s++)
#pragma unroll
                for (int j = 0; j < 8; j++) {
                    float* cc = acc[s][j];
                    const uint32_t* fh = &bh[j >> 1][(j & 1) * 2];
                    const uint32_t* fl = &bl[j >> 1][(j & 1) * 2];
#define MMA_(A, Bf) asm volatile( \
    "mma.sync.aligned.m16n8k16.row.col.f32.bf16.bf16.f32 " \
    "{%0,%1,%2,%3}, {%4,%5,%6,%7}, {%8,%9}, {%0,%1,%2,%3};" \
    : "+f"(cc[0]), "+f"(cc[1]), "+f"(cc[2]), "+f"(cc[3]) \
    : "r"((A)[0]), "r"((A)[1]), "r"((A)[2]), "r"((A)[3]), "r"((Bf)[0]), "r"((Bf)[1]))
                    MMA_(ah[s], fh);
                    MMA_(al[s], fh);
                    MMA_(ah[s], fl);
#undef MMA_
                }
        }
        __syncthreads();
    }

    // ---- lean epilogue: direct fp32 stores to C[n,256] ----
#pragma unroll
    for (int s = 0; s < 2; s++) {
        const int m = m0 + wm * 32 + s * 16 + (lane >> 2);
#pragma unroll
        for (int j = 0; j < 8; j++) {
            const int n = n0 + wn * 64 + j * 8 + (lane & 3) * 2;
            *(float2*)(C + (size_t)m * CO + n)       = make_float2(acc[s][j][0], acc[s][j][1]);
            *(float2*)(C + (size_t)(m + 8) * CO + n) = make_float2(acc[s][j][2], acc[s][j][3]);
        }
    }
}

// ---------------------------------------------------------------------------
// k_stats: per-channel partial sums over y [n,256] (coalesced float4 reads),
// deterministic per-rowblock partials in g_psum/g_psq[j*256 + c].
// ---------------------------------------------------------------------------
__global__ void __launch_bounds__(256) k_stats() {
    __shared__ float4 ss[256], qq[256];
    const int j = blockIdx.x, t = threadIdx.x;
    const int cq = t & 63, rq = t >> 6;
    const float4* y = (const float4*)g_y1;
    float4 s = make_float4(0, 0, 0, 0), q = make_float4(0, 0, 0, 0);
    for (int i = 0; i < 64; i++) {
        const int row = j * 256 + rq * 64 + i;
        const float4 v = y[(size_t)row * 64 + cq];
        s.x += v.x; s.y += v.y; s.z += v.z; s.w += v.w;
        q.x = fmaf(v.x, v.x, q.x); q.y = fmaf(v.y, v.y, q.y);
        q.z = fmaf(v.z, v.z, q.z); q.w = fmaf(v.w, v.w, q.w);
    }
    ss[t] = s; qq[t] = q;
    __syncthreads();
    if (t < 64) {
        float4 a = ss[t], b = ss[t + 64], c = ss[t + 128], d = ss[t + 192];
        float4 e = qq[t], f = qq[t + 64], g = qq[t + 128], h = qq[t + 192];
        float4 so = make_float4((a.x + b.x) + (c.x + d.x), (a.y + b.y) + (c.y + d.y),
                                (a.z + b.z) + (c.z + d.z), (a.w + b.w) + (c.w + d.w));
        float4 qo = make_float4((e.x + f.x) + (g.x + h.x), (e.y + f.y) + (g.y + h.y),
                                (e.z + f.z) + (g.z + h.z), (e.w + f.w) + (g.w + h.w));
        *(float4*)&g_psum[j * 256 + t * 4] = so;
        *(float4*)&g_psq[j * 256 + t * 4]  = qo;
    }
}

// ---------------------------------------------------------------------------
// fold: reduce 256 partials/channel -> folded BN affine
// ---------------------------------------------------------------------------
__global__ void k_fold(const float* __restrict__ gamma, const float* __restrict__ beta,
                       int layer) {
    const int c = threadIdx.x;
    float s = 0.f, q = 0.f;
    for (int j = 0; j < 256; j++) {
        s += g_psum[j * 256 + c];
        q += g_psq[j * 256 + c];
    }
    const float mean = s * (1.f / (float)NS);
    const float var  = q * (1.f / (float)NS) - mean * mean;
    const float a = gamma[c] * rsqrtf(var + 1e-5f);
    const float b = beta[c] - mean * a;
    if (layer == 1) { g_a1[c] = a; g_b1[c] = b; }
    else            { g_a2[c] = a; g_b2[c] = b; }
}

// ---------------------------------------------------------------------------
// x2 = split(relu(a1*y1 + b1))
// ---------------------------------------------------------------------------
__global__ void __launch_bounds__(256) k_x2() {
    const size_t i = (size_t)blockIdx.x * 256 + threadIdx.x;
    const size_t row = i >> 6;
    const int cq = (int)(i & 63), c0 = cq * 4;
    float4 v = ((const float4*)g_y1)[row * 64 + cq];
    const float4 a = *(const float4*)&g_a1[c0];
    const float4 b = *(const float4*)&g_b1[c0];
    v.x = fmaxf(fmaf(a.x, v.x, b.x), 0.f);
    v.y = fmaxf(fmaf(a.y, v.y, b.y), 0.f);
    v.z = fmaxf(fmaf(a.z, v.z, b.z), 0.f);
    v.w = fmaxf(fmaf(a.w, v.w, b.w), 0.f);
    uint32_t h0, l0, h1, l1, h2, l2, h3, l3;
    split_bf16(v.x, h0, l0); split_bf16(v.y, h1, l1);
    split_bf16(v.z, h2, l2); split_bf16(v.w, h3, l3);
    const size_t o = row * CO + c0;
    *(uint2*)(g_x2h + o) = make_uint2(h0 | (h1 << 16), h2 | (h3 << 16));
    *(uint2*)(g_x2l + o) = make_uint2(l0 | (l1 << 16), l2 | (l3 << 16));
}

// ---------------------------------------------------------------------------
// finalize: out[b,o,n] = relu(a2*y2[n,o] + b2)
// ---------------------------------------------------------------------------
__global__ void k_finalize(float* __restrict__ out) {
    __shared__ float t[32][33];
    const int b = blockIdx.z, o0 = blockIdx.y * 32, n0 = blockIdx.x * 32;
    const int tx = threadIdx.x, ty = threadIdx.y;
    const float a = g_a2[o0 + tx], bb = g_b2[o0 + tx];
#pragma unroll
    for (int i = 0; i < 4; i++) {
        const int n = n0 + ty + i * 8;
        const float v = g_y1[(size_t)(b * NPT + n) * CO + o0 + tx];
        t[tx][ty + i * 8] = fmaxf(fmaf(a, v, bb), 0.f);
    }
    __syncthreads();
#pragma unroll
    for (int i = 0; i < 4; i++)
        out[((size_t)b * CO + o0 + ty + i * 8) * NPT + n0 + tx] = t[ty + i * 8][tx];
}

// ---------------------------------------------------------------------------
// Launch
// ---------------------------------------------------------------------------
extern "C" void kernel_launch(void* const* d_in, const int* in_sizes, int n_in,
                              void* d_out, int out_size) {
    const float* xyz1    = (const float*)d_in[0];
    const float* xyz2    = (const float*)d_in[1];
    const float* points1 = (const float*)d_in[2];
    const float* points2 = (const float*)d_in[3];
    const float* W1      = (const float*)d_in[4];
    const float* g1      = (const float*)d_in[6];
    const float* be1     = (const float*)d_in[7];
    const float* W2      = (const float*)d_in[8];
    const float* g2      = (const float*)d_in[10];
    const float* be2     = (const float*)d_in[11];
    float* out = (float*)d_out;

    cudaFuncSetAttribute(k_mma<1>, cudaFuncAttributeMaxDynamicSharedMemorySize, MMA_SMEM);
    cudaFuncSetAttribute(k_mma<2>, cudaFuncAttributeMaxDynamicSharedMemorySize, MMA_SMEM);

    k_wsplit<<<640, 256>>>(W1, W2);
    k_tp2<<<dim3(32, 4, 16), dim3(32, 8)>>>(points2);
    k_tp1<<<dim3(128, 8, 16), dim3(32, 8)>>>(points1);
    k_nn<<<dim3(32, 16), 256>>>(xyz1, xyz2);
    k_gather<<<8192, 256>>>();
    k_mma<1><<<dim3(2, 512), 256, MMA_SMEM>>>();
    k_stats<<<256, 256>>>();
    k_fold<<<1, 256>>>(g1, be1, 1);
    k_x2<<<16384, 256>>>();
    k_mma<2><<<dim3(2, 512), 256, MMA_SMEM>>>();
    k_stats<<<256, 256>>>();
    k_fold<<<1, 256>>>(g2, be2, 2);
    k_finalize<<<dim3(128, 8, 16), dim3(32, 8)>>>(out);
}